// round 5
// baseline (speedup 1.0000x reference)
#include <cuda_runtime.h>

// SpMM: y = x @ W^T, W in CSR with uniform 128 nnz/row.
//   x:       [512, 2048] f32
//   data:    [262144]    f32
//   indices: [262144]    i32  (column ids, sorted per row, may repeat)
//   indptr:  [2049]      i32
//   y (out): [512, 2048] f32
//
// Strategy: token-chunked shared-memory staging.
//   grid = (16 row-groups, 32 token-chunks); block = 512 threads.
//   Each block stages x[tok0..tok0+15][0..2047] (128 KB) into smem, then
//   128 rows x 4 token-quads of threads gather via LDS.128 and accumulate
//   float4. Writeback is warp-coalesced into y[tok][row].

#define NTOK   512
#define NIN    2048
#define NOUT   2048
#define CH     16                      // tokens per chunk
#define NCHUNK (NTOK / CH)             // 32
#define RPB    128                     // rows per block
#define RGRP   (NOUT / RPB)            // 16
#define THREADS 512
#define SMEM_WORDS (NIN * CH)          // 32768 floats = 128 KB

// smem layout: column `col` occupies 16 consecutive words (4 token-quads),
// with the quad slot XOR-swizzled by (col>>1)&3 so that staging stores
// (consecutive cols, fixed quad) are bank-conflict-free.
__device__ __forceinline__ int sx_word(int col, int q) {
    return (col << 4) + (((q ^ (col >> 1)) & 3) << 2);
}

__global__ void __launch_bounds__(THREADS, 1)
spmm_csr_kernel(const float* __restrict__ x,
                const float* __restrict__ data,
                const int*   __restrict__ indices,
                const int*   __restrict__ indptr,
                float*       __restrict__ y)
{
    extern __shared__ float s_x[];

    const int tid  = threadIdx.x;
    const int tok0 = blockIdx.y * CH;

    // ---------------- stage x chunk into smem ----------------
    // Units: (q, col), q in [0,4), col in [0,2048). One float4 per unit
    // holding tokens tok0 + 4q + {0,1,2,3} at column col.
    // Consecutive threads -> consecutive col (same q): LDGs coalesce to
    // 128B lines per component; STS.128 is conflict-free via the swizzle.
    #pragma unroll
    for (int it = 0; it < (NIN * 4) / THREADS; ++it) {
        const int i   = tid + it * THREADS;
        const int q   = i >> 11;          // i / 2048
        const int col = i & (NIN - 1);
        const float* xp = x + (size_t)(tok0 + (q << 2)) * NIN + col;
        float4 v;
        v.x = __ldg(xp);
        v.y = __ldg(xp + NIN);
        v.z = __ldg(xp + 2 * NIN);
        v.w = __ldg(xp + 3 * NIN);
        *reinterpret_cast<float4*>(&s_x[sx_word(col, q)]) = v;
    }
    __syncthreads();

    // ---------------- gather + accumulate ----------------
    // thread -> (row_sub, token-quad tg). Warp = 8 rows x 4 quads, so the
    // 4 lanes sharing a row broadcast-load the same (w, col) pair.
    const int tg      = tid & 3;
    const int row_sub = tid >> 2;
    const int row     = blockIdx.x * RPB + row_sub;

    int       k    = __ldg(&indptr[row]);
    const int kend = __ldg(&indptr[row + 1]);

    float4 acc = make_float4(0.f, 0.f, 0.f, 0.f);

    #pragma unroll 4
    for (; k < kend; ++k) {
        const float w   = __ldg(&data[k]);
        const int   col = __ldg(&indices[k]);
        const float4 v  = *reinterpret_cast<const float4*>(&s_x[sx_word(col, tg)]);
        acc.x = fmaf(w, v.x, acc.x);
        acc.y = fmaf(w, v.y, acc.y);
        acc.z = fmaf(w, v.z, acc.z);
        acc.w = fmaf(w, v.w, acc.w);
    }

    // ---------------- writeback ----------------
    // y[tok][row], tok = tok0 + 4*tg + j. For a fixed j, the 8 lanes with
    // consecutive row_sub (stride-4 lane ids) write 8 consecutive rows of
    // the same token -> each STG.32 fills whole 32B sectors.
    float* yp = y + (size_t)(tok0 + (tg << 2)) * NOUT + row;
    yp[0]            = acc.x;
    yp[NOUT]         = acc.y;
    yp[2 * (size_t)NOUT] = acc.z;
    yp[3 * (size_t)NOUT] = acc.w;
}

extern "C" void kernel_launch(void* const* d_in, const int* in_sizes, int n_in,
                              void* d_out, int out_size)
{
    const float* x       = (const float*)d_in[0];
    const float* data    = (const float*)d_in[1];
    const int*   indices = (const int*)d_in[2];
    const int*   indptr  = (const int*)d_in[3];
    float*       y       = (float*)d_out;

    // Opt in to >48KB dynamic smem (idempotent; not a stream op, capture-safe).
    cudaFuncSetAttribute(spmm_csr_kernel,
                         cudaFuncAttributeMaxDynamicSharedMemorySize,
                         SMEM_WORDS * (int)sizeof(float));

    dim3 grid(RGRP, NCHUNK);
    spmm_csr_kernel<<<grid, THREADS, SMEM_WORDS * sizeof(float)>>>(
        x, data, indices, indptr, y);
}

// round 8
// speedup vs baseline: 2.1554x; 2.1554x over previous
#include <cuda_runtime.h>

// SpMM: y = x @ W^T, W in CSR with uniform 128 nnz/row.
//   x:       [512, 2048] f32
//   data:    [262144]    f32
//   indices: [262144]    i32  (sorted per row, duplicates sum)
//   indptr:  [2049]      i32
//   y (out): [512, 2048] f32
//
// R6 change vs R5: the per-iteration scalar data/indices LDGs (8 lines /
// warp-instr, ~16 L1 wavefronts/iter — the measured bottleneck) are replaced
// by one vectorized float4+int4 LDG pair per 16 k's per row, distributed to
// the 4 token-quad lanes via __shfl_sync. Gather path (swizzled 128KB x
// stage, LDS.128) unchanged — it was already near the smem-crossbar floor.

#define NTOK   512
#define NIN    2048
#define NOUT   2048
#define CH     16                      // tokens per chunk
#define NCHUNK (NTOK / CH)             // 32
#define RPB    128                     // rows per block
#define RGRP   (NOUT / RPB)            // 16
#define THREADS 512
#define SMEM_WORDS (NIN * CH)          // 32768 floats = 128 KB

// Column `col` occupies 16 consecutive words (4 token-quads); quad slot is
// XOR-swizzled so staging STS.128 are conflict-free and the 4 quad-chunks of
// a column tile its 64B half without intra-column conflicts.
__device__ __forceinline__ int sx_word(int col, int q) {
    return (col << 4) + (((q ^ (col >> 1)) & 3) << 2);
}

__device__ __forceinline__ float f4c(const float4& v, int c) {
    return c == 0 ? v.x : c == 1 ? v.y : c == 2 ? v.z : v.w;
}
__device__ __forceinline__ int i4c(const int4& v, int c) {
    return c == 0 ? v.x : c == 1 ? v.y : c == 2 ? v.z : v.w;
}

__global__ void __launch_bounds__(THREADS, 1)
spmm_csr_kernel(const float* __restrict__ x,
                const float* __restrict__ data,
                const int*   __restrict__ indices,
                const int*   __restrict__ indptr,
                float*       __restrict__ y)
{
    extern __shared__ float s_x[];

    const int tid  = threadIdx.x;
    const int tok0 = blockIdx.y * CH;

    // ---------------- stage x chunk into smem (unchanged) ----------------
    #pragma unroll
    for (int it = 0; it < (NIN * 4) / THREADS; ++it) {
        const int i   = tid + it * THREADS;
        const int q   = i >> 11;
        const int col = i & (NIN - 1);
        const float* xp = x + (size_t)(tok0 + (q << 2)) * NIN + col;
        float4 v;
        v.x = __ldg(xp);
        v.y = __ldg(xp + NIN);
        v.z = __ldg(xp + 2 * NIN);
        v.w = __ldg(xp + 3 * NIN);
        *reinterpret_cast<float4*>(&s_x[sx_word(col, q)]) = v;
    }
    __syncthreads();

    // ---------------- gather + accumulate ----------------
    const int lane    = tid & 31;
    const int tg      = tid & 3;          // token quad
    const int row_sub = tid >> 2;         // 0..127
    const int row     = blockIdx.x * RPB + row_sub;

    const int base = __ldg(&indptr[row]);             // = row*128 here
    const int cnt  = __ldg(&indptr[row + 1]) - base;  // = 128

    float4 acc = make_float4(0.f, 0.f, 0.f, 0.f);

    for (int kc = 0; kc < cnt; kc += 16) {
        // Each tg lane owns 4 consecutive k's of this row's 16-k chunk.
        // Per warp-LDG.128: 8 rows x 64B contiguous -> 16 sectors (vs 8
        // scattered lines per scalar LDG before).
        const int ko = base + kc + (tg << 2);
        const float4 d4 = *reinterpret_cast<const float4*>(&data[ko]);
        const int4   i4 = *reinterpret_cast<const int4*>(&indices[ko]);

        #pragma unroll
        for (int j = 0; j < 16; ++j) {
            const int src = (lane & ~3) | (j >> 2);   // same row, quad j>>2
            const float w   = __shfl_sync(0xffffffffu, f4c(d4, j & 3), src);
            const int   col = __shfl_sync(0xffffffffu, i4c(i4, j & 3), src);
            const float4 v = *reinterpret_cast<const float4*>(&s_x[sx_word(col, tg)]);
            acc.x = fmaf(w, v.x, acc.x);
            acc.y = fmaf(w, v.y, acc.y);
            acc.z = fmaf(w, v.z, acc.z);
            acc.w = fmaf(w, v.w, acc.w);
        }
    }

    // ---------------- writeback (unchanged, sector-coalesced) ----------------
    float* yp = y + (size_t)(tok0 + (tg << 2)) * NOUT + row;
    yp[0]                = acc.x;
    yp[NOUT]             = acc.y;
    yp[2 * (size_t)NOUT] = acc.z;
    yp[3 * (size_t)NOUT] = acc.w;
}

extern "C" void kernel_launch(void* const* d_in, const int* in_sizes, int n_in,
                              void* d_out, int out_size)
{
    const float* x       = (const float*)d_in[0];
    const float* data    = (const float*)d_in[1];
    const int*   indices = (const int*)d_in[2];
    const int*   indptr  = (const int*)d_in[3];
    float*       y       = (float*)d_out;

    cudaFuncSetAttribute(spmm_csr_kernel,
                         cudaFuncAttributeMaxDynamicSharedMemorySize,
                         SMEM_WORDS * (int)sizeof(float));

    dim3 grid(RGRP, NCHUNK);
    spmm_csr_kernel<<<grid, THREADS, SMEM_WORDS * sizeof(float)>>>(
        x, data, indices, indptr, y);
}